// round 3
// baseline (speedup 1.0000x reference)
#include <cuda_runtime.h>
#include <math.h>

#define BB   64
#define CC   64
#define LSIG 8192
#define LFFT 4096
#define FF   4097
#define NN   3
#define HIDN 128
#define KK   3

#define RSQRT_L 0.011048543456039806f  /* 1/sqrt(8192) */

// ---------------- scratch (static device globals; no allocation) ------------
__device__ float  g_fxR[(size_t)BB * CC * FF];
__device__ float  g_fxI[(size_t)BB * CC * FF];
__device__ float2 g_tw[FF];                 // exp(-i*pi*k/4096), k=0..4096
__device__ float  g_S [2 * BB * HIDN];
__device__ float  g_h0[2 * BB * HIDN];
__device__ float  g_hE[2 * BB * HIDN];
__device__ float  g_Cc[2 * BB * NN];

// ---------------- helpers ---------------------------------------------------
__device__ __forceinline__ float2 cmul(float2 a, float2 b) {
    return make_float2(a.x * b.x - a.y * b.y, a.x * b.y + a.y * b.x);
}
__device__ __forceinline__ float selu_f(float v) {
    const float a = 1.6732632423543772f, s = 1.0507009873554805f;
    return v > 0.f ? s * v : s * a * (expf(v) - 1.f);
}

// ---------------- twiddle table ---------------------------------------------
__global__ void twiddle_init_kernel() {
    int k = blockIdx.x * blockDim.x + threadIdx.x;
    if (k <= LFFT) {
        float s, c;
        sincospif((float)k / (float)LFFT, &s, &c);  // angle = pi*k/4096
        g_tw[k] = make_float2(c, -s);               // exp(-i*angle)
    }
}

__global__ void zero_S_kernel() {
    int i = blockIdx.x * blockDim.x + threadIdx.x;
    if (i < 2 * BB * HIDN) g_S[i] = 0.f;
}

// ---------------- forward rfft (ortho) --------------------------------------
__global__ __launch_bounds__(256) void fwd_fft_kernel(const float* __restrict__ x) {
    __shared__ float2 sd[LFFT];
    const int row = blockIdx.x;  // b*CC + c
    const int tid = threadIdx.x;
    const float2* xr = (const float2*)(x + (size_t)row * LSIG);

    // pack x[2i],x[2i+1] -> z[i], bit-reversed store
    for (int i = tid; i < LFFT; i += 256) {
        float2 v = xr[i];
        sd[__brev(i) >> 20] = v;
    }
    __syncthreads();

    // 12 radix-2 DIT stages
    for (int s = 1; s <= 12; s++) {
        const int half = 1 << (s - 1);
        const int tsh  = 13 - s;
        for (int t = tid; t < LFFT / 2; t += 256) {
            int j  = t & (half - 1);
            int i0 = ((t >> (s - 1)) << s) + j;
            int i1 = i0 + half;
            float2 w = g_tw[j << tsh];
            float2 u = sd[i0], v = sd[i1];
            float2 wv = cmul(v, w);
            sd[i0] = make_float2(u.x + wv.x, u.y + wv.y);
            sd[i1] = make_float2(u.x - wv.x, u.y - wv.y);
        }
        __syncthreads();
    }

    // unpack to rfft bins 0..4096, ortho scale
    const float sc = 0.5f * RSQRT_L;
    float* fr = g_fxR + (size_t)row * FF;
    float* fi = g_fxI + (size_t)row * FF;
    for (int k = tid; k <= LFFT; k += 256) {
        float2 A  = sd[k & (LFFT - 1)];
        float2 Zr = sd[(LFFT - k) & (LFFT - 1)];
        float2 Ze = make_float2(A.x + Zr.x, A.y - Zr.y);   // 2*Ze
        float2 D  = make_float2(A.x - Zr.x, A.y + Zr.y);
        float2 Zo = make_float2(D.y, -D.x);                // 2*Zo = -i*D
        float2 w  = g_tw[k];
        float2 wZo = cmul(Zo, w);
        fr[k] = sc * (Ze.x + wZo.x);
        fi[k] = sc * (Ze.y + wZo.y);
    }
}

// ---------------- encoder: conv1 + selu + running sum -----------------------
// grid: (33 chunks, BB, 2 branches); block 128 threads (one per hid)
#define LCH 128
#define SMEM_ENC ((192 * 128 + 64 * (LCH + 2)) * 4)

__global__ __launch_bounds__(128) void encoder_kernel(
    const float* __restrict__ wR1, const float* __restrict__ bR1,
    const float* __restrict__ wI1, const float* __restrict__ bI1) {
    extern __shared__ float sm[];
    float* ws = sm;                   // [192][128] transposed weights
    float* xt = sm + 192 * 128;       // [64][LCH+2]

    const int branch = blockIdx.z;
    const int b      = blockIdx.y;
    const int l0     = blockIdx.x * LCH;
    const int tid    = threadIdx.x;

    const float* fx = branch ? g_fxI : g_fxR;
    const float* w1 = branch ? wI1 : wR1;
    const float* b1 = branch ? bI1 : bR1;

    // coalesced weight load, transposed store: ws[j*128+hid] = w1[hid*192+j]
    for (int i = tid; i < 192 * 128; i += 128) {
        int hid = i / 192, j = i % 192;
        ws[j * 128 + hid] = w1[i];
    }
    // fx tile with SAME padding
    for (int i = tid; i < 64 * (LCH + 2); i += 128) {
        int c = i / (LCH + 2), li = i % (LCH + 2);
        int l = l0 - 1 + li;
        float v = (l >= 0 && l < FF) ? fx[((size_t)b * CC + c) * FF + l] : 0.f;
        xt[c * (LCH + 2) + li] = v;
    }
    __syncthreads();

    const int hid  = tid;
    const float bias = b1[hid];
    const int lmax = min(LCH, FF - l0);
    float ssum = 0.f;

    for (int lp = 0; lp < lmax; lp += 2) {
        float a0 = bias, a1 = bias;
        const bool has1 = (lp + 1) < lmax;
        #pragma unroll 16
        for (int c = 0; c < 64; c++) {
            const float* xp = &xt[c * (LCH + 2) + lp];
            float x0 = xp[0], x1 = xp[1], x2 = xp[2], x3 = xp[3];
            const float* wp = &ws[(c * 3) * 128 + hid];
            float w0 = wp[0], w1v = wp[128], w2v = wp[256];
            a0 = fmaf(w0, x0, fmaf(w1v, x1, fmaf(w2v, x2, a0)));
            a1 = fmaf(w0, x1, fmaf(w1v, x2, fmaf(w2v, x3, a1)));
        }
        float h0v = selu_f(a0);
        ssum += h0v;
        int gl = l0 + lp;
        int gidx = (branch * BB + b) * HIDN + hid;
        if (gl == 0)      g_h0[gidx] = h0v;
        if (gl == FF - 1) g_hE[gidx] = h0v;
        if (has1) {
            float h1v = selu_f(a1);
            ssum += h1v;
            if (gl + 1 == FF - 1) g_hE[gidx] = h1v;
        }
    }
    atomicAdd(&g_S[(branch * BB + b) * HIDN + hid], ssum);
}

// ---------------- logits (conv2+mean collapsed) + softmax -------------------
// grid (BB, 2), 128 threads
__global__ __launch_bounds__(128) void logits_kernel(
    const float* __restrict__ wR2, const float* __restrict__ bR2,
    const float* __restrict__ wI2, const float* __restrict__ bI2) {
    const int b = blockIdx.x, branch = blockIdx.y, hid = threadIdx.x;
    const float* w2 = branch ? wI2 : wR2;
    const float* b2 = branch ? bI2 : bR2;

    const int idx = (branch * BB + b) * HIDN + hid;
    float S   = g_S[idx];
    float h0v = g_h0[idx];
    float hEv = g_hE[idx];

    __shared__ float red[NN][HIDN];
    #pragma unroll
    for (int n = 0; n < NN; n++) {
        int base = (n * HIDN + hid) * 3;
        red[n][hid] = w2[base] * (S - hEv) + w2[base + 1] * S + w2[base + 2] * (S - h0v);
    }
    __syncthreads();

    if (hid == 0) {
        float lg[NN];
        #pragma unroll
        for (int n = 0; n < NN; n++) {
            float t = 0.f;
            for (int i = 0; i < HIDN; i++) t += red[n][i];
            lg[n] = b2[n] + t / (float)FF;
        }
        float m = fmaxf(lg[0], fmaxf(lg[1], lg[2]));
        float e0 = expf(lg[0] - m), e1 = expf(lg[1] - m), e2 = expf(lg[2] - m);
        float inv = 1.f / (e0 + e1 + e2);
        g_Cc[(branch * BB + b) * NN + 0] = e0 * inv;
        g_Cc[(branch * BB + b) * NN + 1] = e1 * inv;
        g_Cc[(branch * BB + b) * NN + 2] = e2 * inv;
    }
}

// ---------------- inverse: Y = fx*Kf, irfft (ortho) -------------------------
__global__ __launch_bounds__(256) void inv_fft_kernel(
    const float* __restrict__ param, float* __restrict__ out) {
    __shared__ float2 sd[LFFT];
    const int row = blockIdx.x;
    const int b = row >> 6, c = row & 63;
    const int tid = threadIdx.x;

    float CR[NN], CI[NN];
    #pragma unroll
    for (int n = 0; n < NN; n++) {
        CR[n] = g_Cc[(0 * BB + b) * NN + n];
        CI[n] = g_Cc[(1 * BB + b) * NN + n];
    }

    const float*  fr = g_fxR + (size_t)row * FF;
    const float*  fi = g_fxI + (size_t)row * FF;
    const float2* p2 = (const float2*)param;  // [(n*CC+c)*FF + f] -> (re, im)

    // build packed spectrum Z (without 0.5 factors; folded into final scale)
    for (int k = tid; k < LFFT; k += 256) {
        int m = LFFT - k;  // mirror bin, 1..4096
        // Y[k]
        float fRk = fr[k], fIk = fi[k];
        float KRk = 0.f, KIk = 0.f;
        #pragma unroll
        for (int n = 0; n < NN; n++) {
            float2 w = p2[((size_t)n * CC + c) * FF + k];
            KRk = fmaf(CR[n], w.x, KRk);
            KIk = fmaf(CI[n], w.y, KIk);
        }
        float2 Yk = make_float2(fRk * KRk - fIk * KIk, fRk * KIk + fIk * KRk);
        // Y[m]
        float fRm = fr[m], fIm = fi[m];
        float KRm = 0.f, KIm = 0.f;
        #pragma unroll
        for (int n = 0; n < NN; n++) {
            float2 w = p2[((size_t)n * CC + c) * FF + m];
            KRm = fmaf(CR[n], w.x, KRm);
            KIm = fmaf(CI[n], w.y, KIm);
        }
        float2 Ym = make_float2(fRm * KRm - fIm * KIm, fRm * KIm + fIm * KRm);

        // irfft (c2r) convention: imaginary parts of DC and Nyquist bins are
        // ignored. The k==0 iteration handles both bin 0 (Yk) and bin N (Ym).
        if (k == 0) { Yk.y = 0.f; Ym.y = 0.f; }

        float2 Ze = make_float2(Yk.x + Ym.x, Yk.y - Ym.y);       // 2*Ze
        float2 D  = make_float2(Yk.x - Ym.x, Yk.y + Ym.y);
        float2 tw = g_tw[k];
        float2 Wc = make_float2(tw.x, -tw.y);                    // exp(+i*pi*k/4096)
        float2 Zo = cmul(Wc, D);                                  // 2*Zo
        float2 Z  = make_float2(Ze.x - Zo.y, Ze.y + Zo.x);        // 2*(Ze + i*Zo)
        sd[__brev(k) >> 20] = Z;
    }
    __syncthreads();

    // inverse-direction FFT: conjugate twiddles
    for (int s = 1; s <= 12; s++) {
        const int half = 1 << (s - 1);
        const int tsh  = 13 - s;
        for (int t = tid; t < LFFT / 2; t += 256) {
            int j  = t & (half - 1);
            int i0 = ((t >> (s - 1)) << s) + j;
            int i1 = i0 + half;
            float2 tw = g_tw[j << tsh];
            float2 w  = make_float2(tw.x, -tw.y);
            float2 u = sd[i0], v = sd[i1];
            float2 wv = cmul(v, w);
            sd[i0] = make_float2(u.x + wv.x, u.y + wv.y);
            sd[i1] = make_float2(u.x - wv.x, u.y - wv.y);
        }
        __syncthreads();
    }

    float2* orow = (float2*)(out + (size_t)row * LSIG);
    for (int n = tid; n < LFFT; n += 256) {
        float2 z = sd[n];
        orow[n] = make_float2(RSQRT_L * z.x, RSQRT_L * z.y);
    }
}

// ---------------- launch ----------------------------------------------------
extern "C" void kernel_launch(void* const* d_in, const int* in_sizes, int n_in,
                              void* d_out, int out_size) {
    const float* x    = (const float*)d_in[0];
    const float* prm  = (const float*)d_in[1];
    const float* wR1  = (const float*)d_in[2];
    const float* bR1  = (const float*)d_in[3];
    const float* wR2  = (const float*)d_in[4];
    const float* bR2  = (const float*)d_in[5];
    const float* wI1  = (const float*)d_in[6];
    const float* bI1  = (const float*)d_in[7];
    const float* wI2  = (const float*)d_in[8];
    const float* bI2  = (const float*)d_in[9];
    float* out = (float*)d_out;

    static int smem_attr_set = 0;
    if (!smem_attr_set) {
        cudaFuncSetAttribute(encoder_kernel,
                             cudaFuncAttributeMaxDynamicSharedMemorySize, SMEM_ENC);
        smem_attr_set = 1;
    }

    twiddle_init_kernel<<<17, 256>>>();
    zero_S_kernel<<<64, 256>>>();
    fwd_fft_kernel<<<BB * CC, 256>>>(x);
    encoder_kernel<<<dim3(33, BB, 2), 128, SMEM_ENC>>>(wR1, bR1, wI1, bI1);
    logits_kernel<<<dim3(BB, 2), 128>>>(wR2, bR2, wI2, bI2);
    inv_fft_kernel<<<BB * CC, 256>>>(prm, out);
}

// round 7
// speedup vs baseline: 2.1811x; 2.1811x over previous
#include <cuda_runtime.h>
#include <math.h>
#include <stdint.h>

#define BB   64
#define CC   64
#define LSIG 8192
#define LFFT 4096
#define FF   4097
#define NN   3
#define HIDN 128

#define RSQRT_L 0.011048543456039806f  /* 1/sqrt(8192) */

// ---------------- scratch (static device globals; no allocation) ------------
__device__ float  g_fxR[(size_t)BB * CC * FF];
__device__ float  g_fxI[(size_t)BB * CC * FF];
__device__ float2 g_tw[FF];                 // exp(-i*pi*k/4096)
__device__ float  g_S [2 * BB * HIDN];
__device__ float  g_h0[2 * BB * HIDN];
__device__ float  g_hE[2 * BB * HIDN];
__device__ float  g_Cc[2 * BB * NN];

// ---------------- helpers ---------------------------------------------------
__device__ __forceinline__ float2 cmul(float2 a, float2 b) {
    return make_float2(a.x * b.x - a.y * b.y, a.x * b.y + a.y * b.x);
}
__device__ __forceinline__ float2 cadd(float2 a, float2 b) {
    return make_float2(a.x + b.x, a.y + b.y);
}
__device__ __forceinline__ float2 csub(float2 a, float2 b) {
    return make_float2(a.x - b.x, a.y - b.y);
}
__device__ __forceinline__ float selu_f(float v) {
    const float a = 1.6732632423543772f, s = 1.0507009873554805f;
    return v > 0.f ? s * v : s * a * (expf(v) - 1.f);
}
__device__ __forceinline__ uint32_t to_tf32(float f) {
    uint32_t r;
    asm("cvt.rna.tf32.f32 %0, %1;" : "=r"(r) : "f"(f));
    return r;
}
__device__ __forceinline__ void mma_tf32(float* d, const uint32_t* a, const uint32_t* b) {
    asm volatile(
        "mma.sync.aligned.m16n8k8.row.col.f32.tf32.tf32.f32 "
        "{%0,%1,%2,%3}, {%4,%5,%6,%7}, {%8,%9}, {%0,%1,%2,%3};"
        : "+f"(d[0]), "+f"(d[1]), "+f"(d[2]), "+f"(d[3])
        : "r"(a[0]), "r"(a[1]), "r"(a[2]), "r"(a[3]), "r"(b[0]), "r"(b[1]));
}

// ---------------- twiddle table ---------------------------------------------
__global__ void twiddle_init_kernel() {
    int k = blockIdx.x * blockDim.x + threadIdx.x;
    if (k <= LFFT) {
        float s, c;
        sincospif((float)k / (float)LFFT, &s, &c);
        g_tw[k] = make_float2(c, -s);
    }
}

__global__ void zero_S_kernel() {
    int i = blockIdx.x * blockDim.x + threadIdx.x;
    if (i < 2 * BB * HIDN) g_S[i] = 0.f;
}

// ---------------- forward rfft (ortho) --------------------------------------
__global__ __launch_bounds__(256) void fwd_fft_kernel(const float* __restrict__ x) {
    __shared__ float2 sd[LFFT];
    const int row = blockIdx.x;
    const int tid = threadIdx.x;
    const float2* xr = (const float2*)(x + (size_t)row * LSIG);

    for (int i = tid; i < LFFT; i += 256) {
        float2 v = xr[i];
        sd[__brev(i) >> 20] = v;
    }
    __syncthreads();

    // 6 fused stage-pairs (radix-2 x2 per barrier)
    for (int s = 1; s <= 12; s += 2) {
        const int half = 1 << (s - 1);
        const int tshA = 13 - s;
        const int tshB = 12 - s;
        for (int t = tid; t < LFFT / 4; t += 256) {
            int j = t & (half - 1);
            int g = t >> (s - 1);
            int base = g * (half << 2) + j;
            float2 a = sd[base],            bb = sd[base + half];
            float2 cc = sd[base + 2*half],  dd = sd[base + 3*half];
            float2 w1 = g_tw[j << tshA];
            float2 wb = cmul(bb, w1), wd = cmul(dd, w1);
            float2 u0 = cadd(a, wb),  v0 = csub(a, wb);
            float2 u1 = cadd(cc, wd), v1 = csub(cc, wd);
            float2 w2a = g_tw[j << tshB];
            float2 w2b = make_float2(w2a.y, -w2a.x);   // g_tw[.. + 2048] = -i*w2a
            float2 t0 = cmul(u1, w2a);
            float2 t1 = cmul(v1, w2b);
            sd[base]            = cadd(u0, t0);
            sd[base + 2*half]   = csub(u0, t0);
            sd[base + half]     = cadd(v0, t1);
            sd[base + 3*half]   = csub(v0, t1);
        }
        __syncthreads();
    }

    const float sc = 0.5f * RSQRT_L;
    float* fr = g_fxR + (size_t)row * FF;
    float* fi = g_fxI + (size_t)row * FF;
    for (int k = tid; k <= LFFT; k += 256) {
        float2 A  = sd[k & (LFFT - 1)];
        float2 Zr = sd[(LFFT - k) & (LFFT - 1)];
        float2 Ze = make_float2(A.x + Zr.x, A.y - Zr.y);
        float2 D  = make_float2(A.x - Zr.x, A.y + Zr.y);
        float2 Zo = make_float2(D.y, -D.x);
        float2 w  = g_tw[k];
        float2 wZo = cmul(Zo, w);
        fr[k] = sc * (Ze.x + wZo.x);
        fi[k] = sc * (Ze.y + wZo.y);
    }
}

// ---------------- encoder conv1 via mma.sync TF32 ---------------------------
#define XA_PITCH 68
#define XA_ROWS  130
#define WB_PITCH 136
#define XA_WORDS (XA_ROWS * XA_PITCH)
#define WB_WORDS (3 * 64 * WB_PITCH)
#define SMEM_ENC ((XA_WORDS + WB_WORDS) * 4)

__global__ __launch_bounds__(256) void encoder_mma_kernel(
    const float* __restrict__ wR1, const float* __restrict__ bR1,
    const float* __restrict__ wI1, const float* __restrict__ bI1) {
    extern __shared__ uint32_t sm[];
    uint32_t* XA = sm;
    uint32_t* WB = sm + XA_WORDS;

    const int branch = blockIdx.z;
    const int b      = blockIdx.y;
    const int l0     = blockIdx.x * 128;
    const int tid    = threadIdx.x;
    const int lane   = tid & 31;
    const int warp   = tid >> 5;
    const int wm     = warp & 3;
    const int wn     = warp >> 2;
    const int tig    = lane & 3;
    const int grp    = lane >> 2;

    const float* fx = branch ? g_fxI : g_fxR;
    const float* w1 = branch ? wI1 : wR1;
    const float* b1 = branch ? bI1 : bR1;

    for (int i = tid; i < 24576; i += 256) {
        int hid = i / 192, rem = i - hid * 192;
        int c = rem / 3, k = rem - c * 3;
        WB[(k * 64 + c) * WB_PITCH + hid] = to_tf32(w1[i]);
    }
    const float* fxb = fx + (size_t)b * CC * FF;
    for (int i = tid; i < 64 * 132; i += 256) {
        int c = i / 132, p = i - c * 132;
        if (p < XA_ROWS) {
            int l = l0 - 1 + p;
            float v = (l >= 0 && l < FF) ? fxb[(size_t)c * FF + l] : 0.f;
            XA[p * XA_PITCH + c] = to_tf32(v);
        }
    }
    __syncthreads();

    float acc[2][8][4];
    #pragma unroll
    for (int ms = 0; ms < 2; ms++)
        #pragma unroll
        for (int ns = 0; ns < 8; ns++)
            #pragma unroll
            for (int q = 0; q < 4; q++) acc[ms][ns][q] = 0.f;

    #pragma unroll
    for (int tap = 0; tap < 3; tap++) {
        for (int kc = 0; kc < 8; kc++) {
            const int kcol = kc * 8 + tig;
            uint32_t afrag[2][4];
            #pragma unroll
            for (int ms = 0; ms < 2; ms++) {
                int r0 = wm * 32 + ms * 16 + grp + tap;
                afrag[ms][0] = XA[(r0    ) * XA_PITCH + kcol    ];
                afrag[ms][1] = XA[(r0 + 8) * XA_PITCH + kcol    ];
                afrag[ms][2] = XA[(r0    ) * XA_PITCH + kcol + 4];
                afrag[ms][3] = XA[(r0 + 8) * XA_PITCH + kcol + 4];
            }
            const uint32_t* wbase = WB + (tap * 64 + kc * 8) * WB_PITCH;
            #pragma unroll
            for (int ns = 0; ns < 8; ns++) {
                int n = wn * 64 + ns * 8 + grp;
                uint32_t bfrag[2];
                bfrag[0] = wbase[(tig    ) * WB_PITCH + n];
                bfrag[1] = wbase[(tig + 4) * WB_PITCH + n];
                mma_tf32(acc[0][ns], afrag[0], bfrag);
                mma_tf32(acc[1][ns], afrag[1], bfrag);
            }
        }
    }

    const int gbase = (branch * BB + b) * HIDN;
    #pragma unroll
    for (int ns = 0; ns < 8; ns++) {
        int colb = wn * 64 + ns * 8 + 2 * tig;
        float bias0 = __ldg(&b1[colb]);
        float bias1 = __ldg(&b1[colb + 1]);
        float s0 = 0.f, s1 = 0.f;
        #pragma unroll
        for (int ms = 0; ms < 2; ms++) {
            #pragma unroll
            for (int rr = 0; rr < 2; rr++) {
                int l = l0 + wm * 32 + ms * 16 + grp + rr * 8;
                float v0 = selu_f(acc[ms][ns][rr * 2 + 0] + bias0);
                float v1 = selu_f(acc[ms][ns][rr * 2 + 1] + bias1);
                if (l <= 4096) { s0 += v0; s1 += v1; }
                if (l == 0)    { g_h0[gbase + colb] = v0; g_h0[gbase + colb + 1] = v1; }
                if (l == 4096) { g_hE[gbase + colb] = v0; g_hE[gbase + colb + 1] = v1; }
            }
        }
        s0 += __shfl_xor_sync(0xffffffffu, s0, 4);
        s0 += __shfl_xor_sync(0xffffffffu, s0, 8);
        s0 += __shfl_xor_sync(0xffffffffu, s0, 16);
        s1 += __shfl_xor_sync(0xffffffffu, s1, 4);
        s1 += __shfl_xor_sync(0xffffffffu, s1, 8);
        s1 += __shfl_xor_sync(0xffffffffu, s1, 16);
        if (grp == 0) {
            atomicAdd(&g_S[gbase + colb], s0);
            atomicAdd(&g_S[gbase + colb + 1], s1);
        }
    }
}

// ---------------- logits (conv2+mean collapsed) + softmax -------------------
__global__ __launch_bounds__(128) void logits_kernel(
    const float* __restrict__ wR2, const float* __restrict__ bR2,
    const float* __restrict__ wI2, const float* __restrict__ bI2) {
    const int b = blockIdx.x, branch = blockIdx.y, hid = threadIdx.x;
    const float* w2 = branch ? wI2 : wR2;
    const float* b2 = branch ? bI2 : bR2;

    const int idx = (branch * BB + b) * HIDN + hid;
    float S   = g_S[idx];
    float h0v = g_h0[idx];
    float hEv = g_hE[idx];

    __shared__ float red[NN][HIDN];
    #pragma unroll
    for (int n = 0; n < NN; n++) {
        int base = (n * HIDN + hid) * 3;
        red[n][hid] = w2[base] * (S - hEv) + w2[base + 1] * S + w2[base + 2] * (S - h0v);
    }
    __syncthreads();

    if (hid == 0) {
        float lg[NN];
        #pragma unroll
        for (int n = 0; n < NN; n++) {
            float t = 0.f;
            for (int i = 0; i < HIDN; i++) t += red[n][i];
            lg[n] = b2[n] + t / (float)FF;
        }
        float m = fmaxf(lg[0], fmaxf(lg[1], lg[2]));
        float e0 = expf(lg[0] - m), e1 = expf(lg[1] - m), e2 = expf(lg[2] - m);
        float inv = 1.f / (e0 + e1 + e2);
        g_Cc[(branch * BB + b) * NN + 0] = e0 * inv;
        g_Cc[(branch * BB + b) * NN + 1] = e1 * inv;
        g_Cc[(branch * BB + b) * NN + 2] = e2 * inv;
    }
}

// ---------------- inverse: Y = fx*Kf, irfft (ortho) -------------------------
__global__ __launch_bounds__(256) void inv_fft_kernel(
    const float* __restrict__ param, float* __restrict__ out) {
    __shared__ float2 sd[LFFT];
    const int row = blockIdx.x;
    const int b = row >> 6, c = row & 63;
    const int tid = threadIdx.x;

    float CR[NN], CI[NN];
    #pragma unroll
    for (int n = 0; n < NN; n++) {
        CR[n] = g_Cc[(0 * BB + b) * NN + n];
        CI[n] = g_Cc[(1 * BB + b) * NN + n];
    }

    const float*  fr = g_fxR + (size_t)row * FF;
    const float*  fi = g_fxI + (size_t)row * FF;
    const float2* p2 = (const float2*)param;

    for (int k = tid; k < LFFT; k += 256) {
        int m = LFFT - k;
        float fRk = fr[k], fIk = fi[k];
        float KRk = 0.f, KIk = 0.f;
        #pragma unroll
        for (int n = 0; n < NN; n++) {
            float2 w = p2[((size_t)n * CC + c) * FF + k];
            KRk = fmaf(CR[n], w.x, KRk);
            KIk = fmaf(CI[n], w.y, KIk);
        }
        float2 Yk = make_float2(fRk * KRk - fIk * KIk, fRk * KIk + fIk * KRk);
        float fRm = fr[m], fIm = fi[m];
        float KRm = 0.f, KIm = 0.f;
        #pragma unroll
        for (int n = 0; n < NN; n++) {
            float2 w = p2[((size_t)n * CC + c) * FF + m];
            KRm = fmaf(CR[n], w.x, KRm);
            KIm = fmaf(CI[n], w.y, KIm);
        }
        float2 Ym = make_float2(fRm * KRm - fIm * KIm, fRm * KIm + fIm * KRm);

        if (k == 0) { Yk.y = 0.f; Ym.y = 0.f; }

        float2 Ze = make_float2(Yk.x + Ym.x, Yk.y - Ym.y);
        float2 D  = make_float2(Yk.x - Ym.x, Yk.y + Ym.y);
        float2 tw = g_tw[k];
        float2 Wc = make_float2(tw.x, -tw.y);
        float2 Zo = cmul(Wc, D);
        float2 Z  = make_float2(Ze.x - Zo.y, Ze.y + Zo.x);
        sd[__brev(k) >> 20] = Z;
    }
    __syncthreads();

    // 6 fused stage-pairs, conjugated twiddles
    for (int s = 1; s <= 12; s += 2) {
        const int half = 1 << (s - 1);
        const int tshA = 13 - s;
        const int tshB = 12 - s;
        for (int t = tid; t < LFFT / 4; t += 256) {
            int j = t & (half - 1);
            int g = t >> (s - 1);
            int base = g * (half << 2) + j;
            float2 a = sd[base],            bb = sd[base + half];
            float2 cc = sd[base + 2*half],  dd = sd[base + 3*half];
            float2 t1w = g_tw[j << tshA];
            float2 w1 = make_float2(t1w.x, -t1w.y);          // conj
            float2 wb = cmul(bb, w1), wd = cmul(dd, w1);
            float2 u0 = cadd(a, wb),  v0 = csub(a, wb);
            float2 u1 = cadd(cc, wd), v1 = csub(cc, wd);
            float2 t2w = g_tw[j << tshB];
            float2 w2a = make_float2(t2w.x, -t2w.y);         // conj
            float2 w2b = make_float2(-w2a.y, w2a.x);         // +i * w2a
            float2 t0 = cmul(u1, w2a);
            float2 t1 = cmul(v1, w2b);
            sd[base]            = cadd(u0, t0);
            sd[base + 2*half]   = csub(u0, t0);
            sd[base + half]     = cadd(v0, t1);
            sd[base + 3*half]   = csub(v0, t1);
        }
        __syncthreads();
    }

    float2* orow = (float2*)(out + (size_t)row * LSIG);
    for (int n = tid; n < LFFT; n += 256) {
        float2 z = sd[n];
        orow[n] = make_float2(RSQRT_L * z.x, RSQRT_L * z.y);
    }
}

// ---------------- launch ----------------------------------------------------
extern "C" void kernel_launch(void* const* d_in, const int* in_sizes, int n_in,
                              void* d_out, int out_size) {
    const float* x    = (const float*)d_in[0];
    const float* prm  = (const float*)d_in[1];
    const float* wR1  = (const float*)d_in[2];
    const float* bR1  = (const float*)d_in[3];
    const float* wR2  = (const float*)d_in[4];
    const float* bR2  = (const float*)d_in[5];
    const float* wI1  = (const float*)d_in[6];
    const float* bI1  = (const float*)d_in[7];
    const float* wI2  = (const float*)d_in[8];
    const float* bI2  = (const float*)d_in[9];
    float* out = (float*)d_out;

    static int smem_attr_set = 0;
    if (!smem_attr_set) {
        cudaFuncSetAttribute(encoder_mma_kernel,
                             cudaFuncAttributeMaxDynamicSharedMemorySize, SMEM_ENC);
        smem_attr_set = 1;
    }

    twiddle_init_kernel<<<17, 256>>>();
    zero_S_kernel<<<64, 256>>>();
    fwd_fft_kernel<<<BB * CC, 256>>>(x);
    encoder_mma_kernel<<<dim3(33, BB, 2), 256, SMEM_ENC>>>(wR1, bR1, wI1, bI1);
    logits_kernel<<<dim3(BB, 2), 128>>>(wR2, bR2, wI2, bI2);
    inv_fft_kernel<<<BB * CC, 256>>>(prm, out);
}

// round 9
// speedup vs baseline: 2.6098x; 1.1965x over previous
#include <cuda_runtime.h>
#include <math.h>
#include <stdint.h>

#define BB   64
#define CC   64
#define LSIG 8192
#define LFFT 4096
#define FF   4097
#define NN   3
#define HIDN 128

#define RSQRT_L 0.011048543456039806f  /* 1/sqrt(8192) */

// ---------------- scratch (static device globals; no allocation) ------------
__device__ float  g_fxR[(size_t)BB * CC * FF];
__device__ float  g_fxI[(size_t)BB * CC * FF];
__device__ float2 g_tw[FF];                 // exp(-i*pi*k/4096)
__device__ float  g_S [2 * BB * HIDN];
__device__ float  g_h0[2 * BB * HIDN];
__device__ float  g_hE[2 * BB * HIDN];
__device__ float  g_Cc[2 * BB * NN];

// ---------------- helpers ---------------------------------------------------
__device__ __forceinline__ float2 cmul(float2 a, float2 b) {
    return make_float2(a.x * b.x - a.y * b.y, a.x * b.y + a.y * b.x);
}
__device__ __forceinline__ float2 cadd(float2 a, float2 b) {
    return make_float2(a.x + b.x, a.y + b.y);
}
__device__ __forceinline__ float2 csub(float2 a, float2 b) {
    return make_float2(a.x - b.x, a.y - b.y);
}
__device__ __forceinline__ float selu_f(float v) {
    const float a = 1.6732632423543772f, s = 1.0507009873554805f;
    return v > 0.f ? s * v : s * a * (expf(v) - 1.f);
}
__device__ __forceinline__ uint32_t to_tf32(float f) {
    uint32_t r;
    asm("cvt.rna.tf32.f32 %0, %1;" : "=r"(r) : "f"(f));
    return r;
}
__device__ __forceinline__ void mma_tf32(float* d, const uint32_t* a, const uint32_t* b) {
    asm volatile(
        "mma.sync.aligned.m16n8k8.row.col.f32.tf32.tf32.f32 "
        "{%0,%1,%2,%3}, {%4,%5,%6,%7}, {%8,%9}, {%0,%1,%2,%3};"
        : "+f"(d[0]), "+f"(d[1]), "+f"(d[2]), "+f"(d[3])
        : "r"(a[0]), "r"(a[1]), "r"(a[2]), "r"(a[3]), "r"(b[0]), "r"(b[1]));
}

// ---------------- twiddle table ---------------------------------------------
__global__ void twiddle_init_kernel() {
    int k = blockIdx.x * blockDim.x + threadIdx.x;
    if (k <= LFFT) {
        float s, c;
        sincospif((float)k / (float)LFFT, &s, &c);
        g_tw[k] = make_float2(c, -s);
    }
}

__global__ void zero_S_kernel() {
    int i = blockIdx.x * blockDim.x + threadIdx.x;
    if (i < 2 * BB * HIDN) g_S[i] = 0.f;
}

// ---------------- forward rfft (ortho) --------------------------------------
__global__ __launch_bounds__(256) void fwd_fft_kernel(const float* __restrict__ x) {
    __shared__ float2 sd[LFFT];
    const int row = blockIdx.x;
    const int tid = threadIdx.x;
    const float2* xr = (const float2*)(x + (size_t)row * LSIG);

    for (int i = tid; i < LFFT; i += 256) {
        float2 v = xr[i];
        sd[__brev(i) >> 20] = v;
    }
    __syncthreads();

    for (int s = 1; s <= 12; s += 2) {
        const int half = 1 << (s - 1);
        const int tshA = 13 - s;
        const int tshB = 12 - s;
        for (int t = tid; t < LFFT / 4; t += 256) {
            int j = t & (half - 1);
            int g = t >> (s - 1);
            int base = g * (half << 2) + j;
            float2 a = sd[base],            bb = sd[base + half];
            float2 cc = sd[base + 2*half],  dd = sd[base + 3*half];
            float2 w1 = g_tw[j << tshA];
            float2 wb = cmul(bb, w1), wd = cmul(dd, w1);
            float2 u0 = cadd(a, wb),  v0 = csub(a, wb);
            float2 u1 = cadd(cc, wd), v1 = csub(cc, wd);
            float2 w2a = g_tw[j << tshB];
            float2 w2b = make_float2(w2a.y, -w2a.x);
            float2 t0 = cmul(u1, w2a);
            float2 t1 = cmul(v1, w2b);
            sd[base]            = cadd(u0, t0);
            sd[base + 2*half]   = csub(u0, t0);
            sd[base + half]     = cadd(v0, t1);
            sd[base + 3*half]   = csub(v0, t1);
        }
        __syncthreads();
    }

    const float sc = 0.5f * RSQRT_L;
    float* fr = g_fxR + (size_t)row * FF;
    float* fi = g_fxI + (size_t)row * FF;
    for (int k = tid; k <= LFFT; k += 256) {
        float2 A  = sd[k & (LFFT - 1)];
        float2 Zr = sd[(LFFT - k) & (LFFT - 1)];
        float2 Ze = make_float2(A.x + Zr.x, A.y - Zr.y);
        float2 D  = make_float2(A.x - Zr.x, A.y + Zr.y);
        float2 Zo = make_float2(D.y, -D.x);
        float2 w  = g_tw[k];
        float2 wZo = cmul(Zo, w);
        fr[k] = sc * (Ze.x + wZo.x);
        fi[k] = sc * (Ze.y + wZo.y);
    }
}

// ---------------- encoder conv1 via mma.sync TF32 (hid-split) ---------------
// grid (33, BB, 4): z -> branch = z>>1, hh = z&1 (which 64-hid half)
// block 256 thr, tile 128 pos x 64 hid; warp: wm=warp&3 (32 pos), wn=warp>>2 (32 hid)
#define XA_PITCH 68
#define XA_ROWS  130
#define WB_PITCH 72
#define XA_WORDS (XA_ROWS * XA_PITCH)
#define WB_WORDS (3 * 64 * WB_PITCH)
#define SMEM_ENC ((XA_WORDS + WB_WORDS) * 4)

__global__ __launch_bounds__(256) void encoder_mma_kernel(
    const float* __restrict__ wR1, const float* __restrict__ bR1,
    const float* __restrict__ wI1, const float* __restrict__ bI1) {
    extern __shared__ uint32_t sm[];
    uint32_t* XA = sm;
    uint32_t* WB = sm + XA_WORDS;

    const int branch = blockIdx.z >> 1;
    const int hh     = blockIdx.z & 1;
    const int b      = blockIdx.y;
    const int l0     = blockIdx.x * 128;
    const int tid    = threadIdx.x;
    const int lane   = tid & 31;
    const int warp   = tid >> 5;
    const int wm     = warp & 3;   // 32-position slice
    const int wn     = warp >> 2;  // 32-hid slice (0/1)
    const int tig    = lane & 3;
    const int grp    = lane >> 2;

    const float* fx = branch ? g_fxI : g_fxR;
    const float* w1 = branch ? wI1 : wR1;
    const float* b1 = branch ? bI1 : bR1;

    // ---- load this half's weights -> WB[tap][c][hid_l], pitch 72 ----
    // w1 layout: [hid 128][c 64][k 3]; we take hid in [hh*64, hh*64+64)
    const float* w1h = w1 + (size_t)hh * 64 * 192;
    for (int i = tid; i < 64 * 192; i += 256) {
        int hid_l = i / 192, ck = i - hid_l * 192;
        int c = ck / 3, k = ck - c * 3;
        WB[(k * 64 + c) * WB_PITCH + hid_l] = to_tf32(w1h[i]);
    }
    // ---- fx tile -> XA[p][c]; p=0 <-> l0-1 ----
    const float* fxb = fx + (size_t)b * CC * FF;
    for (int i = tid; i < 64 * 132; i += 256) {
        int c = i / 132, p = i - c * 132;
        if (p < XA_ROWS) {
            int l = l0 - 1 + p;
            float v = (l >= 0 && l < FF) ? fxb[(size_t)c * FF + l] : 0.f;
            XA[p * XA_PITCH + c] = to_tf32(v);
        }
    }
    __syncthreads();

    float acc[2][4][4];
    #pragma unroll
    for (int ms = 0; ms < 2; ms++)
        #pragma unroll
        for (int ns = 0; ns < 4; ns++)
            #pragma unroll
            for (int q = 0; q < 4; q++) acc[ms][ns][q] = 0.f;

    // ---- main loop: kc outer, taps fused via shared row loads ----
    for (int kc = 0; kc < 8; kc++) {
        const int kcol = kc * 8 + tig;
        // 12 rows x 2 cols covering ms{0,1} x h{0,1} x tap{0,1,2}
        uint32_t arow[2][2][3][2];
        #pragma unroll
        for (int ms = 0; ms < 2; ms++)
            #pragma unroll
            for (int h = 0; h < 2; h++)
                #pragma unroll
                for (int tap = 0; tap < 3; tap++) {
                    int r = wm * 32 + ms * 16 + h * 8 + tap + grp;
                    arow[ms][h][tap][0] = XA[r * XA_PITCH + kcol];
                    arow[ms][h][tap][1] = XA[r * XA_PITCH + kcol + 4];
                }
        #pragma unroll
        for (int ns = 0; ns < 4; ns++) {
            const int n = wn * 32 + ns * 8 + grp;
            #pragma unroll
            for (int tap = 0; tap < 3; tap++) {
                const uint32_t* wbase = WB + (tap * 64 + kc * 8) * WB_PITCH;
                uint32_t bfrag[2];
                bfrag[0] = wbase[(tig    ) * WB_PITCH + n];
                bfrag[1] = wbase[(tig + 4) * WB_PITCH + n];
                #pragma unroll
                for (int ms = 0; ms < 2; ms++) {
                    uint32_t afrag[4] = {
                        arow[ms][0][tap][0], arow[ms][1][tap][0],
                        arow[ms][0][tap][1], arow[ms][1][tap][1] };
                    mma_tf32(acc[ms][ns], afrag, bfrag);
                }
            }
        }
    }

    // ---- epilogue ----
    const int gbase = (branch * BB + b) * HIDN + hh * 64;
    #pragma unroll
    for (int ns = 0; ns < 4; ns++) {
        int colb = wn * 32 + ns * 8 + 2 * tig;   // local hid (0..63)
        float bias0 = __ldg(&b1[hh * 64 + colb]);
        float bias1 = __ldg(&b1[hh * 64 + colb + 1]);
        float s0 = 0.f, s1 = 0.f;
        #pragma unroll
        for (int ms = 0; ms < 2; ms++) {
            #pragma unroll
            for (int rr = 0; rr < 2; rr++) {
                int l = l0 + wm * 32 + ms * 16 + grp + rr * 8;
                float v0 = selu_f(acc[ms][ns][rr * 2 + 0] + bias0);
                float v1 = selu_f(acc[ms][ns][rr * 2 + 1] + bias1);
                if (l <= 4096) { s0 += v0; s1 += v1; }
                if (l == 0)    { g_h0[gbase + colb] = v0; g_h0[gbase + colb + 1] = v1; }
                if (l == 4096) { g_hE[gbase + colb] = v0; g_hE[gbase + colb + 1] = v1; }
            }
        }
        s0 += __shfl_xor_sync(0xffffffffu, s0, 4);
        s0 += __shfl_xor_sync(0xffffffffu, s0, 8);
        s0 += __shfl_xor_sync(0xffffffffu, s0, 16);
        s1 += __shfl_xor_sync(0xffffffffu, s1, 4);
        s1 += __shfl_xor_sync(0xffffffffu, s1, 8);
        s1 += __shfl_xor_sync(0xffffffffu, s1, 16);
        if (grp == 0) {
            atomicAdd(&g_S[gbase + colb], s0);
            atomicAdd(&g_S[gbase + colb + 1], s1);
        }
    }
}

// ---------------- logits (conv2+mean collapsed) + softmax -------------------
__global__ __launch_bounds__(128) void logits_kernel(
    const float* __restrict__ wR2, const float* __restrict__ bR2,
    const float* __restrict__ wI2, const float* __restrict__ bI2) {
    const int b = blockIdx.x, branch = blockIdx.y, hid = threadIdx.x;
    const float* w2 = branch ? wI2 : wR2;
    const float* b2 = branch ? bI2 : bR2;

    const int idx = (branch * BB + b) * HIDN + hid;
    float S   = g_S[idx];
    float h0v = g_h0[idx];
    float hEv = g_hE[idx];

    __shared__ float red[NN][HIDN];
    #pragma unroll
    for (int n = 0; n < NN; n++) {
        int base = (n * HIDN + hid) * 3;
        red[n][hid] = w2[base] * (S - hEv) + w2[base + 1] * S + w2[base + 2] * (S - h0v);
    }
    __syncthreads();

    if (hid == 0) {
        float lg[NN];
        #pragma unroll
        for (int n = 0; n < NN; n++) {
            float t = 0.f;
            for (int i = 0; i < HIDN; i++) t += red[n][i];
            lg[n] = b2[n] + t / (float)FF;
        }
        float m = fmaxf(lg[0], fmaxf(lg[1], lg[2]));
        float e0 = expf(lg[0] - m), e1 = expf(lg[1] - m), e2 = expf(lg[2] - m);
        float inv = 1.f / (e0 + e1 + e2);
        g_Cc[(branch * BB + b) * NN + 0] = e0 * inv;
        g_Cc[(branch * BB + b) * NN + 1] = e1 * inv;
        g_Cc[(branch * BB + b) * NN + 2] = e2 * inv;
    }
}

// ---------------- inverse: Y = fx*Kf, irfft (ortho) -------------------------
__global__ __launch_bounds__(256) void inv_fft_kernel(
    const float* __restrict__ param, float* __restrict__ out) {
    __shared__ float2 sd[LFFT];
    const int row = blockIdx.x;
    const int b = row >> 6, c = row & 63;
    const int tid = threadIdx.x;

    float CR[NN], CI[NN];
    #pragma unroll
    for (int n = 0; n < NN; n++) {
        CR[n] = g_Cc[(0 * BB + b) * NN + n];
        CI[n] = g_Cc[(1 * BB + b) * NN + n];
    }

    const float*  fr = g_fxR + (size_t)row * FF;
    const float*  fi = g_fxI + (size_t)row * FF;
    const float2* p2 = (const float2*)param;

    for (int k = tid; k < LFFT; k += 256) {
        int m = LFFT - k;
        float fRk = fr[k], fIk = fi[k];
        float KRk = 0.f, KIk = 0.f;
        #pragma unroll
        for (int n = 0; n < NN; n++) {
            float2 w = p2[((size_t)n * CC + c) * FF + k];
            KRk = fmaf(CR[n], w.x, KRk);
            KIk = fmaf(CI[n], w.y, KIk);
        }
        float2 Yk = make_float2(fRk * KRk - fIk * KIk, fRk * KIk + fIk * KRk);
        float fRm = fr[m], fIm = fi[m];
        float KRm = 0.f, KIm = 0.f;
        #pragma unroll
        for (int n = 0; n < NN; n++) {
            float2 w = p2[((size_t)n * CC + c) * FF + m];
            KRm = fmaf(CR[n], w.x, KRm);
            KIm = fmaf(CI[n], w.y, KIm);
        }
        float2 Ym = make_float2(fRm * KRm - fIm * KIm, fRm * KIm + fIm * KRm);

        if (k == 0) { Yk.y = 0.f; Ym.y = 0.f; }

        float2 Ze = make_float2(Yk.x + Ym.x, Yk.y - Ym.y);
        float2 D  = make_float2(Yk.x - Ym.x, Yk.y + Ym.y);
        float2 tw = g_tw[k];
        float2 Wc = make_float2(tw.x, -tw.y);
        float2 Zo = cmul(Wc, D);
        float2 Z  = make_float2(Ze.x - Zo.y, Ze.y + Zo.x);
        sd[__brev(k) >> 20] = Z;
    }
    __syncthreads();

    for (int s = 1; s <= 12; s += 2) {
        const int half = 1 << (s - 1);
        const int tshA = 13 - s;
        const int tshB = 12 - s;
        for (int t = tid; t < LFFT / 4; t += 256) {
            int j = t & (half - 1);
            int g = t >> (s - 1);
            int base = g * (half << 2) + j;
            float2 a = sd[base],            bb = sd[base + half];
            float2 cc = sd[base + 2*half],  dd = sd[base + 3*half];
            float2 t1w = g_tw[j << tshA];
            float2 w1 = make_float2(t1w.x, -t1w.y);
            float2 wb = cmul(bb, w1), wd = cmul(dd, w1);
            float2 u0 = cadd(a, wb),  v0 = csub(a, wb);
            float2 u1 = cadd(cc, wd), v1 = csub(cc, wd);
            float2 t2w = g_tw[j << tshB];
            float2 w2a = make_float2(t2w.x, -t2w.y);
            float2 w2b = make_float2(-w2a.y, w2a.x);
            float2 t0 = cmul(u1, w2a);
            float2 t1 = cmul(v1, w2b);
            sd[base]            = cadd(u0, t0);
            sd[base + 2*half]   = csub(u0, t0);
            sd[base + half]     = cadd(v0, t1);
            sd[base + 3*half]   = csub(v0, t1);
        }
        __syncthreads();
    }

    float2* orow = (float2*)(out + (size_t)row * LSIG);
    for (int n = tid; n < LFFT; n += 256) {
        float2 z = sd[n];
        orow[n] = make_float2(RSQRT_L * z.x, RSQRT_L * z.y);
    }
}

// ---------------- launch ----------------------------------------------------
extern "C" void kernel_launch(void* const* d_in, const int* in_sizes, int n_in,
                              void* d_out, int out_size) {
    const float* x    = (const float*)d_in[0];
    const float* prm  = (const float*)d_in[1];
    const float* wR1  = (const float*)d_in[2];
    const float* bR1  = (const float*)d_in[3];
    const float* wR2  = (const float*)d_in[4];
    const float* bR2  = (const float*)d_in[5];
    const float* wI1  = (const float*)d_in[6];
    const float* bI1  = (const float*)d_in[7];
    const float* wI2  = (const float*)d_in[8];
    const float* bI2  = (const float*)d_in[9];
    float* out = (float*)d_out;

    static int smem_attr_set = 0;
    if (!smem_attr_set) {
        cudaFuncSetAttribute(encoder_mma_kernel,
                             cudaFuncAttributeMaxDynamicSharedMemorySize, SMEM_ENC);
        smem_attr_set = 1;
    }

    twiddle_init_kernel<<<17, 256>>>();
    zero_S_kernel<<<64, 256>>>();
    fwd_fft_kernel<<<BB * CC, 256>>>(x);
    encoder_mma_kernel<<<dim3(33, BB, 4), 256, SMEM_ENC>>>(wR1, bR1, wI1, bI1);
    logits_kernel<<<dim3(BB, 2), 128>>>(wR2, bR2, wI2, bI2);
    inv_fft_kernel<<<BB * CC, 256>>>(prm, out);
}

// round 14
// speedup vs baseline: 2.8856x; 1.1057x over previous
#include <cuda_runtime.h>
#include <cuda_bf16.h>
#include <math.h>
#include <stdint.h>

#define BB   64
#define CC   64
#define LSIG 8192
#define LFFT 4096
#define FF   4097
#define NN   3
#define HIDN 128

#define RSQRT_L 0.011048543456039806f  /* 1/sqrt(8192) */

// ---------------- scratch (static device globals; no allocation) ------------
__device__ float  g_fxR[(size_t)BB * CC * FF];
__device__ float  g_fxI[(size_t)BB * CC * FF];
__device__ float2 g_tw[FF];                 // exp(-i*pi*k/4096)
__device__ float  g_S [2 * BB * HIDN];
__device__ float  g_h0[2 * BB * HIDN];
__device__ float  g_hE[2 * BB * HIDN];
__device__ float  g_Cc[2 * BB * NN];

// ---------------- helpers ---------------------------------------------------
__device__ __forceinline__ float2 cmul(float2 a, float2 b) {
    return make_float2(a.x * b.x - a.y * b.y, a.x * b.y + a.y * b.x);
}
__device__ __forceinline__ float2 cadd(float2 a, float2 b) {
    return make_float2(a.x + b.x, a.y + b.y);
}
__device__ __forceinline__ float2 csub(float2 a, float2 b) {
    return make_float2(a.x - b.x, a.y - b.y);
}
__device__ __forceinline__ float selu_f(float v) {
    const float a = 1.6732632423543772f, s = 1.0507009873554805f;
    return v > 0.f ? s * v : s * a * (expf(v) - 1.f);
}
__device__ __forceinline__ uint32_t pack_bf16x2(float lo, float hi) {
    uint32_t r;
    asm("cvt.rn.bf16x2.f32 %0, %1, %2;" : "=r"(r) : "f"(hi), "f"(lo));
    return r;
}
__device__ __forceinline__ void mma_bf16(float* d, const uint32_t* a, const uint32_t* b) {
    asm volatile(
        "mma.sync.aligned.m16n8k16.row.col.f32.bf16.bf16.f32 "
        "{%0,%1,%2,%3}, {%4,%5,%6,%7}, {%8,%9}, {%0,%1,%2,%3};"
        : "+f"(d[0]), "+f"(d[1]), "+f"(d[2]), "+f"(d[3])
        : "r"(a[0]), "r"(a[1]), "r"(a[2]), "r"(a[3]), "r"(b[0]), "r"(b[1]));
}

// ---------------- twiddle table ---------------------------------------------
__global__ void twiddle_init_kernel() {
    int k = blockIdx.x * blockDim.x + threadIdx.x;
    if (k <= LFFT) {
        float s, c;
        sincospif((float)k / (float)LFFT, &s, &c);
        g_tw[k] = make_float2(c, -s);
    }
}

__global__ void zero_S_kernel() {
    int i = blockIdx.x * blockDim.x + threadIdx.x;
    if (i < 2 * BB * HIDN) g_S[i] = 0.f;
}

// ---------------- forward rfft (ortho) --------------------------------------
__global__ __launch_bounds__(256) void fwd_fft_kernel(const float* __restrict__ x) {
    __shared__ float2 sd[LFFT];
    const int row = blockIdx.x;
    const int tid = threadIdx.x;
    const float2* xr = (const float2*)(x + (size_t)row * LSIG);

    for (int i = tid; i < LFFT; i += 256) {
        float2 v = xr[i];
        sd[__brev(i) >> 20] = v;
    }
    __syncthreads();

    for (int s = 1; s <= 12; s += 2) {
        const int half = 1 << (s - 1);
        const int tshA = 13 - s;
        const int tshB = 12 - s;
        for (int t = tid; t < LFFT / 4; t += 256) {
            int j = t & (half - 1);
            int g = t >> (s - 1);
            int base = g * (half << 2) + j;
            float2 a = sd[base],            bb = sd[base + half];
            float2 cc = sd[base + 2*half],  dd = sd[base + 3*half];
            float2 w1 = g_tw[j << tshA];
            float2 wb = cmul(bb, w1), wd = cmul(dd, w1);
            float2 u0 = cadd(a, wb),  v0 = csub(a, wb);
            float2 u1 = cadd(cc, wd), v1 = csub(cc, wd);
            float2 w2a = g_tw[j << tshB];
            float2 w2b = make_float2(w2a.y, -w2a.x);
            float2 t0 = cmul(u1, w2a);
            float2 t1 = cmul(v1, w2b);
            sd[base]            = cadd(u0, t0);
            sd[base + 2*half]   = csub(u0, t0);
            sd[base + half]     = cadd(v0, t1);
            sd[base + 3*half]   = csub(v0, t1);
        }
        __syncthreads();
    }

    const float sc = 0.5f * RSQRT_L;
    float* fr = g_fxR + (size_t)row * FF;
    float* fi = g_fxI + (size_t)row * FF;
    for (int k = tid; k <= LFFT; k += 256) {
        float2 A  = sd[k & (LFFT - 1)];
        float2 Zr = sd[(LFFT - k) & (LFFT - 1)];
        float2 Ze = make_float2(A.x + Zr.x, A.y - Zr.y);
        float2 D  = make_float2(A.x - Zr.x, A.y + Zr.y);
        float2 Zo = make_float2(D.y, -D.x);
        float2 w  = g_tw[k];
        float2 wZo = cmul(Zo, w);
        fr[k] = sc * (Ze.x + wZo.x);
        fi[k] = sc * (Ze.y + wZo.y);
    }
}

// ---------------- encoder conv1 via mma.sync bf16 (hid-split) ---------------
// grid (33, BB, 4): z -> branch = z>>1, hh = z&1 (64-hid half)
// block 256 thr; tile 128 pos x 64 hid; warp: wm=warp&3 (32 pos), wn=warp>>2 (32 hid)
// XAp[p][cp]: uint32 = bf16x2 (fx[2cp], fx[2cp+1]) at position p, pitch 36
// WBp[tap][cp][hid]: uint32 = bf16x2 (W[hid][2cp][tap], W[hid][2cp+1][tap]), pitch 72
#define XA_PITCH 36
#define XA_ROWS  130
#define WB_PITCH 72
#define XA_WORDS (XA_ROWS * XA_PITCH)
#define WB_WORDS (3 * 32 * WB_PITCH)
#define SMEM_ENC ((XA_WORDS + WB_WORDS) * 4)

__global__ __launch_bounds__(256) void encoder_mma_kernel(
    const float* __restrict__ wR1, const float* __restrict__ bR1,
    const float* __restrict__ wI1, const float* __restrict__ bI1) {
    extern __shared__ uint32_t sm[];
    uint32_t* XA = sm;
    uint32_t* WB = sm + XA_WORDS;

    const int branch = blockIdx.z >> 1;
    const int hh     = blockIdx.z & 1;
    const int b      = blockIdx.y;
    const int l0     = blockIdx.x * 128;
    const int tid    = threadIdx.x;
    const int lane   = tid & 31;
    const int warp   = tid >> 5;
    const int wm     = warp & 3;   // 32-position slice
    const int wn     = warp >> 2;  // 32-hid slice (0/1)
    const int tig    = lane & 3;
    const int grp    = lane >> 2;

    const float* fx = branch ? g_fxI : g_fxR;
    const float* w1 = branch ? wI1 : wR1;
    const float* b1 = branch ? bI1 : bR1;

    // ---- weights -> WBp[tap][cp][hid_l], bf16x2 packed along c ----
    const float* w1h = w1 + (size_t)hh * 64 * 192;   // [hid_l][c][k]
    for (int i = tid; i < 3 * 32 * 64; i += 256) {
        int tap = i / (32 * 64);
        int rem = i - tap * (32 * 64);
        int cp = rem >> 6, hid_l = rem & 63;
        float v0 = w1h[hid_l * 192 + (2 * cp    ) * 3 + tap];
        float v1 = w1h[hid_l * 192 + (2 * cp + 1) * 3 + tap];
        WB[(tap * 32 + cp) * WB_PITCH + hid_l] = pack_bf16x2(v0, v1);
    }
    // ---- fx tile -> XAp[p][cp], coalesced along l ----
    const float* fxb = fx + (size_t)b * CC * FF;
    for (int i = tid; i < 32 * 132; i += 256) {
        int cp = i / 132, p = i - cp * 132;
        if (p < XA_ROWS) {
            int l = l0 - 1 + p;
            bool ok = (l >= 0 && l < FF);
            float v0 = ok ? fxb[(size_t)(2 * cp    ) * FF + l] : 0.f;
            float v1 = ok ? fxb[(size_t)(2 * cp + 1) * FF + l] : 0.f;
            XA[p * XA_PITCH + cp] = pack_bf16x2(v0, v1);
        }
    }
    __syncthreads();

    float acc[2][4][4];
    #pragma unroll
    for (int ms = 0; ms < 2; ms++)
        #pragma unroll
        for (int ns = 0; ns < 4; ns++)
            #pragma unroll
            for (int q = 0; q < 4; q++) acc[ms][ns][q] = 0.f;

    // ---- main loop: 4 chunks of K=16 (cp blocks of 8), taps fused ----
    for (int kc = 0; kc < 4; kc++) {
        const int cp0 = kc * 8 + tig;
        uint32_t arow[2][2][3][2];
        #pragma unroll
        for (int ms = 0; ms < 2; ms++)
            #pragma unroll
            for (int h = 0; h < 2; h++)
                #pragma unroll
                for (int tap = 0; tap < 3; tap++) {
                    int r = wm * 32 + ms * 16 + h * 8 + tap + grp;
                    arow[ms][h][tap][0] = XA[r * XA_PITCH + cp0];
                    arow[ms][h][tap][1] = XA[r * XA_PITCH + cp0 + 4];
                }
        #pragma unroll
        for (int ns = 0; ns < 4; ns++) {
            const int n = wn * 32 + ns * 8 + grp;
            #pragma unroll
            for (int tap = 0; tap < 3; tap++) {
                const uint32_t* wbase = WB + (tap * 32 + kc * 8) * WB_PITCH;
                uint32_t bfrag[2];
                bfrag[0] = wbase[(tig    ) * WB_PITCH + n];
                bfrag[1] = wbase[(tig + 4) * WB_PITCH + n];
                #pragma unroll
                for (int ms = 0; ms < 2; ms++) {
                    uint32_t afrag[4] = {
                        arow[ms][0][tap][0], arow[ms][1][tap][0],
                        arow[ms][0][tap][1], arow[ms][1][tap][1] };
                    mma_bf16(acc[ms][ns], afrag, bfrag);
                }
            }
        }
    }

    // ---- epilogue ----
    const int gbase = (branch * BB + b) * HIDN + hh * 64;
    #pragma unroll
    for (int ns = 0; ns < 4; ns++) {
        int colb = wn * 32 + ns * 8 + 2 * tig;   // local hid (0..63)
        float bias0 = __ldg(&b1[hh * 64 + colb]);
        float bias1 = __ldg(&b1[hh * 64 + colb + 1]);
        float s0 = 0.f, s1 = 0.f;
        #pragma unroll
        for (int ms = 0; ms < 2; ms++) {
            #pragma unroll
            for (int rr = 0; rr < 2; rr++) {
                int l = l0 + wm * 32 + ms * 16 + grp + rr * 8;
                float v0 = selu_f(acc[ms][ns][rr * 2 + 0] + bias0);
                float v1 = selu_f(acc[ms][ns][rr * 2 + 1] + bias1);
                if (l <= 4096) { s0 += v0; s1 += v1; }
                if (l == 0)    { g_h0[gbase + colb] = v0; g_h0[gbase + colb + 1] = v1; }
                if (l == 4096) { g_hE[gbase + colb] = v0; g_hE[gbase + colb + 1] = v1; }
            }
        }
        s0 += __shfl_xor_sync(0xffffffffu, s0, 4);
        s0 += __shfl_xor_sync(0xffffffffu, s0, 8);
        s0 += __shfl_xor_sync(0xffffffffu, s0, 16);
        s1 += __shfl_xor_sync(0xffffffffu, s1, 4);
        s1 += __shfl_xor_sync(0xffffffffu, s1, 8);
        s1 += __shfl_xor_sync(0xffffffffu, s1, 16);
        if (grp == 0) {
            atomicAdd(&g_S[gbase + colb], s0);
            atomicAdd(&g_S[gbase + colb + 1], s1);
        }
    }
}

// ---------------- logits (conv2+mean collapsed) + softmax -------------------
__global__ __launch_bounds__(128) void logits_kernel(
    const float* __restrict__ wR2, const float* __restrict__ bR2,
    const float* __restrict__ wI2, const float* __restrict__ bI2) {
    const int b = blockIdx.x, branch = blockIdx.y, hid = threadIdx.x;
    const float* w2 = branch ? wI2 : wR2;
    const float* b2 = branch ? bI2 : bR2;

    const int idx = (branch * BB + b) * HIDN + hid;
    float S   = g_S[idx];
    float h0v = g_h0[idx];
    float hEv = g_hE[idx];

    __shared__ float red[NN][HIDN];
    #pragma unroll
    for (int n = 0; n < NN; n++) {
        int base = (n * HIDN + hid) * 3;
        red[n][hid] = w2[base] * (S - hEv) + w2[base + 1] * S + w2[base + 2] * (S - h0v);
    }
    __syncthreads();

    if (hid == 0) {
        float lg[NN];
        #pragma unroll
        for (int n = 0; n < NN; n++) {
            float t = 0.f;
            for (int i = 0; i < HIDN; i++) t += red[n][i];
            lg[n] = b2[n] + t / (float)FF;
        }
        float m = fmaxf(lg[0], fmaxf(lg[1], lg[2]));
        float e0 = expf(lg[0] - m), e1 = expf(lg[1] - m), e2 = expf(lg[2] - m);
        float inv = 1.f / (e0 + e1 + e2);
        g_Cc[(branch * BB + b) * NN + 0] = e0 * inv;
        g_Cc[(branch * BB + b) * NN + 1] = e1 * inv;
        g_Cc[(branch * BB + b) * NN + 2] = e2 * inv;
    }
}

// ---------------- inverse: Y = fx*Kf, irfft (ortho) -------------------------
__global__ __launch_bounds__(256) void inv_fft_kernel(
    const float* __restrict__ param, float* __restrict__ out) {
    __shared__ float2 sd[LFFT];
    const int row = blockIdx.x;
    const int b = row >> 6, c = row & 63;
    const int tid = threadIdx.x;

    float CR[NN], CI[NN];
    #pragma unroll
    for (int n = 0; n < NN; n++) {
        CR[n] = g_Cc[(0 * BB + b) * NN + n];
        CI[n] = g_Cc[(1 * BB + b) * NN + n];
    }

    const float*  fr = g_fxR + (size_t)row * FF;
    const float*  fi = g_fxI + (size_t)row * FF;
    const float2* p2 = (const float2*)param;

    for (int k = tid; k < LFFT; k += 256) {
        int m = LFFT - k;
        float fRk = fr[k], fIk = fi[k];
        float KRk = 0.f, KIk = 0.f;
        #pragma unroll
        for (int n = 0; n < NN; n++) {
            float2 w = p2[((size_t)n * CC + c) * FF + k];
            KRk = fmaf(CR[n], w.x, KRk);
            KIk = fmaf(CI[n], w.y, KIk);
        }
        float2 Yk = make_float2(fRk * KRk - fIk * KIk, fRk * KIk + fIk * KRk);
        float fRm = fr[m], fIm = fi[m];
        float KRm = 0.f, KIm = 0.f;
        #pragma unroll
        for (int n = 0; n < NN; n++) {
            float2 w = p2[((size_t)n * CC + c) * FF + m];
            KRm = fmaf(CR[n], w.x, KRm);
            KIm = fmaf(CI[n], w.y, KIm);
        }
        float2 Ym = make_float2(fRm * KRm - fIm * KIm, fRm * KIm + fIm * KRm);

        if (k == 0) { Yk.y = 0.f; Ym.y = 0.f; }

        float2 Ze = make_float2(Yk.x + Ym.x, Yk.y - Ym.y);
        float2 D  = make_float2(Yk.x - Ym.x, Yk.y + Ym.y);
        float2 tw = g_tw[k];
        float2 Wc = make_float2(tw.x, -tw.y);
        float2 Zo = cmul(Wc, D);
        float2 Z  = make_float2(Ze.x - Zo.y, Ze.y + Zo.x);
        sd[__brev(k) >> 20] = Z;
    }
    __syncthreads();

    for (int s = 1; s <= 12; s += 2) {
        const int half = 1 << (s - 1);
        const int tshA = 13 - s;
        const int tshB = 12 - s;
        for (int t = tid; t < LFFT / 4; t += 256) {
            int j = t & (half - 1);
            int g = t >> (s - 1);
            int base = g * (half << 2) + j;
            float2 a = sd[base],            bb = sd[base + half];
            float2 cc = sd[base + 2*half],  dd = sd[base + 3*half];
            float2 t1w = g_tw[j << tshA];
            float2 w1 = make_float2(t1w.x, -t1w.y);
            float2 wb = cmul(bb, w1), wd = cmul(dd, w1);
            float2 u0 = cadd(a, wb),  v0 = csub(a, wb);
            float2 u1 = cadd(cc, wd), v1 = csub(cc, wd);
            float2 t2w = g_tw[j << tshB];
            float2 w2a = make_float2(t2w.x, -t2w.y);
            float2 w2b = make_float2(-w2a.y, w2a.x);
            float2 t0 = cmul(u1, w2a);
            float2 t1 = cmul(v1, w2b);
            sd[base]            = cadd(u0, t0);
            sd[base + 2*half]   = csub(u0, t0);
            sd[base + half]     = cadd(v0, t1);
            sd[base + 3*half]   = csub(v0, t1);
        }
        __syncthreads();
    }

    float2* orow = (float2*)(out + (size_t)row * LSIG);
    for (int n = tid; n < LFFT; n += 256) {
        float2 z = sd[n];
        orow[n] = make_float2(RSQRT_L * z.x, RSQRT_L * z.y);
    }
}

// ---------------- launch ----------------------------------------------------
extern "C" void kernel_launch(void* const* d_in, const int* in_sizes, int n_in,
                              void* d_out, int out_size) {
    const float* x    = (const float*)d_in[0];
    const float* prm  = (const float*)d_in[1];
    const float* wR1  = (const float*)d_in[2];
    const float* bR1  = (const float*)d_in[3];
    const float* wR2  = (const float*)d_in[4];
    const float* bR2  = (const float*)d_in[5];
    const float* wI1  = (const float*)d_in[6];
    const float* bI1  = (const float*)d_in[7];
    const float* wI2  = (const float*)d_in[8];
    const float* bI2  = (const float*)d_in[9];
    float* out = (float*)d_out;

    static int smem_attr_set = 0;
    if (!smem_attr_set) {
        cudaFuncSetAttribute(encoder_mma_kernel,
                             cudaFuncAttributeMaxDynamicSharedMemorySize, SMEM_ENC);
        smem_attr_set = 1;
    }

    twiddle_init_kernel<<<17, 256>>>();
    zero_S_kernel<<<64, 256>>>();
    fwd_fft_kernel<<<BB * CC, 256>>>(x);
    encoder_mma_kernel<<<dim3(33, BB, 4), 256, SMEM_ENC>>>(wR1, bR1, wI1, bI1);
    logits_kernel<<<dim3(BB, 2), 128>>>(wR2, bR2, wI2, bI2);
    inv_fft_kernel<<<BB * CC, 256>>>(prm, out);
}

// round 15
// speedup vs baseline: 3.7974x; 1.3160x over previous
#include <cuda_runtime.h>
#include <cuda_bf16.h>
#include <math.h>
#include <stdint.h>

#define BB   64
#define CC   64
#define LSIG 8192
#define LFFT 4096
#define FF   4097
#define NN   3
#define HIDN 128

#define RSQRT_L 0.011048543456039806f  /* 1/sqrt(8192) */

// ---------------- scratch (static device globals; no allocation) ------------
__device__ float  g_fxR[(size_t)BB * CC * FF];
__device__ float  g_fxI[(size_t)BB * CC * FF];
__device__ float2 g_tw[FF];                 // exp(-i*pi*k/4096)
__device__ float  g_S [2 * BB * HIDN];
__device__ float  g_h0[2 * BB * HIDN];
__device__ float  g_hE[2 * BB * HIDN];
__device__ float  g_Cc[2 * BB * NN];

// ---------------- helpers ---------------------------------------------------
__device__ __forceinline__ float2 cmul(float2 a, float2 b) {
    return make_float2(a.x * b.x - a.y * b.y, a.x * b.y + a.y * b.x);
}
__device__ __forceinline__ float2 cadd(float2 a, float2 b) {
    return make_float2(a.x + b.x, a.y + b.y);
}
__device__ __forceinline__ float2 csub(float2 a, float2 b) {
    return make_float2(a.x - b.x, a.y - b.y);
}
__device__ __forceinline__ float selu_f(float v) {
    const float a = 1.6732632423543772f, s = 1.0507009873554805f;
    return v > 0.f ? s * v : s * a * (expf(v) - 1.f);
}
__device__ __forceinline__ uint32_t pack_bf16x2(float lo, float hi) {
    uint32_t r;
    asm("cvt.rn.bf16x2.f32 %0, %1, %2;" : "=r"(r) : "f"(hi), "f"(lo));
    return r;
}
__device__ __forceinline__ void mma_bf16(float* d, const uint32_t* a, const uint32_t* b) {
    asm volatile(
        "mma.sync.aligned.m16n8k16.row.col.f32.bf16.bf16.f32 "
        "{%0,%1,%2,%3}, {%4,%5,%6,%7}, {%8,%9}, {%0,%1,%2,%3};"
        : "+f"(d[0]), "+f"(d[1]), "+f"(d[2]), "+f"(d[3])
        : "r"(a[0]), "r"(a[1]), "r"(a[2]), "r"(a[3]), "r"(b[0]), "r"(b[1]));
}

// ---------------- twiddle table ---------------------------------------------
__global__ void twiddle_init_kernel() {
    int k = blockIdx.x * blockDim.x + threadIdx.x;
    if (k <= LFFT) {
        float s, c;
        sincospif((float)k / (float)LFFT, &s, &c);
        g_tw[k] = make_float2(c, -s);
    }
}

__global__ void zero_S_kernel() {
    int i = blockIdx.x * blockDim.x + threadIdx.x;
    if (i < 2 * BB * HIDN) g_S[i] = 0.f;
}

// ---------------- forward rfft (ortho) --------------------------------------
__global__ __launch_bounds__(256) void fwd_fft_kernel(const float* __restrict__ x) {
    __shared__ float2 sd[LFFT];
    const int row = blockIdx.x;
    const int tid = threadIdx.x;
    const float2* xr = (const float2*)(x + (size_t)row * LSIG);

    for (int i = tid; i < LFFT; i += 256) {
        float2 v = xr[i];
        sd[__brev(i) >> 20] = v;
    }
    __syncthreads();

    for (int s = 1; s <= 12; s += 2) {
        const int half = 1 << (s - 1);
        const int tshA = 13 - s;
        const int tshB = 12 - s;
        for (int t = tid; t < LFFT / 4; t += 256) {
            int j = t & (half - 1);
            int g = t >> (s - 1);
            int base = g * (half << 2) + j;
            float2 a = sd[base],            bb = sd[base + half];
            float2 cc = sd[base + 2*half],  dd = sd[base + 3*half];
            float2 w1 = g_tw[j << tshA];
            float2 wb = cmul(bb, w1), wd = cmul(dd, w1);
            float2 u0 = cadd(a, wb),  v0 = csub(a, wb);
            float2 u1 = cadd(cc, wd), v1 = csub(cc, wd);
            float2 w2a = g_tw[j << tshB];
            float2 w2b = make_float2(w2a.y, -w2a.x);
            float2 t0 = cmul(u1, w2a);
            float2 t1 = cmul(v1, w2b);
            sd[base]            = cadd(u0, t0);
            sd[base + 2*half]   = csub(u0, t0);
            sd[base + half]     = cadd(v0, t1);
            sd[base + 3*half]   = csub(v0, t1);
        }
        __syncthreads();
    }

    const float sc = 0.5f * RSQRT_L;
    float* fr = g_fxR + (size_t)row * FF;
    float* fi = g_fxI + (size_t)row * FF;
    for (int k = tid; k <= LFFT; k += 256) {
        float2 A  = sd[k & (LFFT - 1)];
        float2 Zr = sd[(LFFT - k) & (LFFT - 1)];
        float2 Ze = make_float2(A.x + Zr.x, A.y - Zr.y);
        float2 D  = make_float2(A.x - Zr.x, A.y + Zr.y);
        float2 Zo = make_float2(D.y, -D.x);
        float2 w  = g_tw[k];
        float2 wZo = cmul(Zo, w);
        fr[k] = sc * (Ze.x + wZo.x);
        fi[k] = sc * (Ze.y + wZo.y);
    }
}

// ---------------- encoder conv1 via mma.sync bf16 (hid-split) ---------------
// grid (33, BB, 4): z -> branch = z>>1, hh = z&1 (64-hid half)
// block 256 thr; tile 128 pos x 64 hid; warp: wm=warp&3 (32 pos), wn=warp>>2 (32 hid)
// XAp[p][cp]: uint32 = bf16x2 (fx[2cp], fx[2cp+1]) at position p, pitch 36
// WB[hid][cp*3 + tap]: uint32 = bf16x2 (W[hid][2cp][tap], W[hid][2cp+1][tap]), pitch 100
#define XA_PITCH 36
#define XA_ROWS  130
#define WB_PITCH 100
#define XA_WORDS (XA_ROWS * XA_PITCH)
#define WB_WORDS (64 * WB_PITCH)
#define SMEM_ENC ((XA_WORDS + WB_WORDS) * 4)

__global__ __launch_bounds__(256) void encoder_mma_kernel(
    const float* __restrict__ wR1, const float* __restrict__ bR1,
    const float* __restrict__ wI1, const float* __restrict__ bI1) {
    extern __shared__ uint32_t sm[];
    uint32_t* XA = sm;
    uint32_t* WB = sm + XA_WORDS;

    const int branch = blockIdx.z >> 1;
    const int hh     = blockIdx.z & 1;
    const int b      = blockIdx.y;
    const int l0     = blockIdx.x * 128;
    const int tid    = threadIdx.x;
    const int lane   = tid & 31;
    const int warp   = tid >> 5;
    const int wm     = warp & 3;   // 32-position slice
    const int wn     = warp >> 2;  // 32-hid slice (0/1)
    const int tig    = lane & 3;
    const int grp    = lane >> 2;

    const float* fx = branch ? g_fxI : g_fxR;
    const float* w1 = branch ? wI1 : wR1;
    const float* b1 = branch ? bI1 : bR1;

    // ---- weights -> WB[hid][cp*3+tap], coalesced global reads ----
    // w1h layout [hid_l][c][k]; read offsets 2*rem - tap (near-consecutive),
    // store offsets = rem exactly (conflict-free consecutive words).
    const float* w1h = w1 + (size_t)hh * 64 * 192;
    for (int i = tid; i < 64 * 96; i += 256) {
        int hid_l = i / 96;
        int rem = i - hid_l * 96;          // = cp*3 + tap
        int cp = rem / 3, tap = rem - cp * 3;
        float v0 = w1h[hid_l * 192 + cp * 6 + tap];
        float v1 = w1h[hid_l * 192 + cp * 6 + 3 + tap];
        WB[hid_l * WB_PITCH + rem] = pack_bf16x2(v0, v1);
    }
    // ---- fx tile -> XAp[p][cp], coalesced along l ----
    const float* fxb = fx + (size_t)b * CC * FF;
    for (int i = tid; i < 32 * 132; i += 256) {
        int cp = i / 132, p = i - cp * 132;
        if (p < XA_ROWS) {
            int l = l0 - 1 + p;
            bool ok = (l >= 0 && l < FF);
            float v0 = ok ? fxb[(size_t)(2 * cp    ) * FF + l] : 0.f;
            float v1 = ok ? fxb[(size_t)(2 * cp + 1) * FF + l] : 0.f;
            XA[p * XA_PITCH + cp] = pack_bf16x2(v0, v1);
        }
    }
    __syncthreads();

    float acc[2][4][4];
    #pragma unroll
    for (int ms = 0; ms < 2; ms++)
        #pragma unroll
        for (int ns = 0; ns < 4; ns++)
            #pragma unroll
            for (int q = 0; q < 4; q++) acc[ms][ns][q] = 0.f;

    // ---- main loop: 4 chunks of K=16 (cp blocks of 8), taps fused ----
    for (int kc = 0; kc < 4; kc++) {
        const int cp0 = kc * 8 + tig;
        uint32_t arow[2][2][3][2];
        #pragma unroll
        for (int ms = 0; ms < 2; ms++)
            #pragma unroll
            for (int h = 0; h < 2; h++)
                #pragma unroll
                for (int tap = 0; tap < 3; tap++) {
                    int r = wm * 32 + ms * 16 + h * 8 + tap + grp;
                    arow[ms][h][tap][0] = XA[r * XA_PITCH + cp0];
                    arow[ms][h][tap][1] = XA[r * XA_PITCH + cp0 + 4];
                }
        #pragma unroll
        for (int ns = 0; ns < 4; ns++) {
            const int n = wn * 32 + ns * 8 + grp;
            #pragma unroll
            for (int tap = 0; tap < 3; tap++) {
                const int kb = (kc * 8 + tig) * 3 + tap;
                uint32_t bfrag[2];
                bfrag[0] = WB[n * WB_PITCH + kb];
                bfrag[1] = WB[n * WB_PITCH + kb + 12];   // (tig+4)*3 + tap
                #pragma unroll
                for (int ms = 0; ms < 2; ms++) {
                    uint32_t afrag[4] = {
                        arow[ms][0][tap][0], arow[ms][1][tap][0],
                        arow[ms][0][tap][1], arow[ms][1][tap][1] };
                    mma_bf16(acc[ms][ns], afrag, bfrag);
                }
            }
        }
    }

    // ---- epilogue ----
    const int gbase = (branch * BB + b) * HIDN + hh * 64;
    #pragma unroll
    for (int ns = 0; ns < 4; ns++) {
        int colb = wn * 32 + ns * 8 + 2 * tig;   // local hid (0..63)
        float bias0 = __ldg(&b1[hh * 64 + colb]);
        float bias1 = __ldg(&b1[hh * 64 + colb + 1]);
        float s0 = 0.f, s1 = 0.f;
        #pragma unroll
        for (int ms = 0; ms < 2; ms++) {
            #pragma unroll
            for (int rr = 0; rr < 2; rr++) {
                int l = l0 + wm * 32 + ms * 16 + grp + rr * 8;
                float v0 = selu_f(acc[ms][ns][rr * 2 + 0] + bias0);
                float v1 = selu_f(acc[ms][ns][rr * 2 + 1] + bias1);
                if (l <= 4096) { s0 += v0; s1 += v1; }
                if (l == 0)    { g_h0[gbase + colb] = v0; g_h0[gbase + colb + 1] = v1; }
                if (l == 4096) { g_hE[gbase + colb] = v0; g_hE[gbase + colb + 1] = v1; }
            }
        }
        s0 += __shfl_xor_sync(0xffffffffu, s0, 4);
        s0 += __shfl_xor_sync(0xffffffffu, s0, 8);
        s0 += __shfl_xor_sync(0xffffffffu, s0, 16);
        s1 += __shfl_xor_sync(0xffffffffu, s1, 4);
        s1 += __shfl_xor_sync(0xffffffffu, s1, 8);
        s1 += __shfl_xor_sync(0xffffffffu, s1, 16);
        if (grp == 0) {
            atomicAdd(&g_S[gbase + colb], s0);
            atomicAdd(&g_S[gbase + colb + 1], s1);
        }
    }
}

// ---------------- logits (conv2+mean collapsed) + softmax -------------------
__global__ __launch_bounds__(128) void logits_kernel(
    const float* __restrict__ wR2, const float* __restrict__ bR2,
    const float* __restrict__ wI2, const float* __restrict__ bI2) {
    const int b = blockIdx.x, branch = blockIdx.y, hid = threadIdx.x;
    const float* w2 = branch ? wI2 : wR2;
    const float* b2 = branch ? bI2 : bR2;

    const int idx = (branch * BB + b) * HIDN + hid;
    float S   = g_S[idx];
    float h0v = g_h0[idx];
    float hEv = g_hE[idx];

    __shared__ float red[NN][HIDN];
    #pragma unroll
    for (int n = 0; n < NN; n++) {
        int base = (n * HIDN + hid) * 3;
        red[n][hid] = w2[base] * (S - hEv) + w2[base + 1] * S + w2[base + 2] * (S - h0v);
    }
    __syncthreads();

    if (hid == 0) {
        float lg[NN];
        #pragma unroll
        for (int n = 0; n < NN; n++) {
            float t = 0.f;
            for (int i = 0; i < HIDN; i++) t += red[n][i];
            lg[n] = b2[n] + t / (float)FF;
        }
        float m = fmaxf(lg[0], fmaxf(lg[1], lg[2]));
        float e0 = expf(lg[0] - m), e1 = expf(lg[1] - m), e2 = expf(lg[2] - m);
        float inv = 1.f / (e0 + e1 + e2);
        g_Cc[(branch * BB + b) * NN + 0] = e0 * inv;
        g_Cc[(branch * BB + b) * NN + 1] = e1 * inv;
        g_Cc[(branch * BB + b) * NN + 2] = e2 * inv;
    }
}

// ---------------- inverse: Y = fx*Kf, irfft (ortho) -------------------------
__global__ __launch_bounds__(256) void inv_fft_kernel(
    const float* __restrict__ param, float* __restrict__ out) {
    __shared__ float2 sd[LFFT];
    const int row = blockIdx.x;
    const int b = row >> 6, c = row & 63;
    const int tid = threadIdx.x;

    float CR[NN], CI[NN];
    #pragma unroll
    for (int n = 0; n < NN; n++) {
        CR[n] = g_Cc[(0 * BB + b) * NN + n];
        CI[n] = g_Cc[(1 * BB + b) * NN + n];
    }

    const float*  fr = g_fxR + (size_t)row * FF;
    const float*  fi = g_fxI + (size_t)row * FF;
    const float2* p2 = (const float2*)param;

    for (int k = tid; k < LFFT; k += 256) {
        int m = LFFT - k;
        float fRk = fr[k], fIk = fi[k];
        float KRk = 0.f, KIk = 0.f;
        #pragma unroll
        for (int n = 0; n < NN; n++) {
            float2 w = p2[((size_t)n * CC + c) * FF + k];
            KRk = fmaf(CR[n], w.x, KRk);
            KIk = fmaf(CI[n], w.y, KIk);
        }
        float2 Yk = make_float2(fRk * KRk - fIk * KIk, fRk * KIk + fIk * KRk);
        float fRm = fr[m], fIm = fi[m];
        float KRm = 0.f, KIm = 0.f;
        #pragma unroll
        for (int n = 0; n < NN; n++) {
            float2 w = p2[((size_t)n * CC + c) * FF + m];
            KRm = fmaf(CR[n], w.x, KRm);
            KIm = fmaf(CI[n], w.y, KIm);
        }
        float2 Ym = make_float2(fRm * KRm - fIm * KIm, fRm * KIm + fIm * KRm);

        if (k == 0) { Yk.y = 0.f; Ym.y = 0.f; }

        float2 Ze = make_float2(Yk.x + Ym.x, Yk.y - Ym.y);
        float2 D  = make_float2(Yk.x - Ym.x, Yk.y + Ym.y);
        float2 tw = g_tw[k];
        float2 Wc = make_float2(tw.x, -tw.y);
        float2 Zo = cmul(Wc, D);
        float2 Z  = make_float2(Ze.x - Zo.y, Ze.y + Zo.x);
        sd[__brev(k) >> 20] = Z;
    }
    __syncthreads();

    for (int s = 1; s <= 12; s += 2) {
        const int half = 1 << (s - 1);
        const int tshA = 13 - s;
        const int tshB = 12 - s;
        for (int t = tid; t < LFFT / 4; t += 256) {
            int j = t & (half - 1);
            int g = t >> (s - 1);
            int base = g * (half << 2) + j;
            float2 a = sd[base],            bb = sd[base + half];
            float2 cc = sd[base + 2*half],  dd = sd[base + 3*half];
            float2 t1w = g_tw[j << tshA];
            float2 w1 = make_float2(t1w.x, -t1w.y);
            float2 wb = cmul(bb, w1), wd = cmul(dd, w1);
            float2 u0 = cadd(a, wb),  v0 = csub(a, wb);
            float2 u1 = cadd(cc, wd), v1 = csub(cc, wd);
            float2 t2w = g_tw[j << tshB];
            float2 w2a = make_float2(t2w.x, -t2w.y);
            float2 w2b = make_float2(-w2a.y, w2a.x);
            float2 t0 = cmul(u1, w2a);
            float2 t1 = cmul(v1, w2b);
            sd[base]            = cadd(u0, t0);
            sd[base + 2*half]   = csub(u0, t0);
            sd[base + half]     = cadd(v0, t1);
            sd[base + 3*half]   = csub(v0, t1);
        }
        __syncthreads();
    }

    float2* orow = (float2*)(out + (size_t)row * LSIG);
    for (int n = tid; n < LFFT; n += 256) {
        float2 z = sd[n];
        orow[n] = make_float2(RSQRT_L * z.x, RSQRT_L * z.y);
    }
}

// ---------------- launch ----------------------------------------------------
extern "C" void kernel_launch(void* const* d_in, const int* in_sizes, int n_in,
                              void* d_out, int out_size) {
    const float* x    = (const float*)d_in[0];
    const float* prm  = (const float*)d_in[1];
    const float* wR1  = (const float*)d_in[2];
    const float* bR1  = (const float*)d_in[3];
    const float* wR2  = (const float*)d_in[4];
    const float* bR2  = (const float*)d_in[5];
    const float* wI1  = (const float*)d_in[6];
    const float* bI1  = (const float*)d_in[7];
    const float* wI2  = (const float*)d_in[8];
    const float* bI2  = (const float*)d_in[9];
    float* out = (float*)d_out;

    static int smem_attr_set = 0;
    if (!smem_attr_set) {
        cudaFuncSetAttribute(encoder_mma_kernel,
                             cudaFuncAttributeMaxDynamicSharedMemorySize, SMEM_ENC);
        smem_attr_set = 1;
    }

    twiddle_init_kernel<<<17, 256>>>();
    zero_S_kernel<<<64, 256>>>();
    fwd_fft_kernel<<<BB * CC, 256>>>(x);
    encoder_mma_kernel<<<dim3(33, BB, 4), 256, SMEM_ENC>>>(wR1, bR1, wI1, bI1);
    logits_kernel<<<dim3(BB, 2), 128>>>(wR2, bR2, wI2, bI2);
    inv_fft_kernel<<<BB * CC, 256>>>(prm, out);
}